// round 1
// baseline (speedup 1.0000x reference)
#include <cuda_runtime.h>
#include <cstdint>

// Problem dims
// B=8, T=4096, D=512, DI=1024, K=7; BT = 32768 rows.

// ---------------------------------------------------------------------------
// Scratch: one big __device__ array (no allocation allowed). ~960 MB.
// Offsets in floats.
#define OFF_XZ 0ull                  // 32768 x 2048  (x_proj | z)
#define OFF_CF 67108864ull           // 32768 x 1024  conv fwd (shifted)
#define OFF_CB 100663296ull          // 32768 x 1024  conv bwd (shift baked in)
#define OFF_YF 134217728ull          // 32768 x 1024  silu(proj_fwd)
#define OFF_YB 167772160ull          // 32768 x 1024  silu(proj_bwd)
#define OFF_Y  201326592ull          // 32768 x 1024  gated combine
#define OFF_H  234881024ull          // 32768 x 512   residual + out_proj
#define SCRATCH_FLOATS 251658240ull

__device__ float g_scratch[SCRATCH_FLOATS];

__device__ __forceinline__ float siluf(float v) {
    return v / (1.0f + expf(-v));
}

// ---------------------------------------------------------------------------
// Generic TN GEMM: C[m,n] = sum_k A[m,k] * B[n,k]
// A: M x K row-major, B: N x K row-major. 128x128 tile, BK=16, 256 threads,
// 8x8 per-thread micro-tile.
// mode 0: plain store
// mode 1: v += bias[n]; v = (t==0)    ? 0 : silu(v)   (fwd mixer epilogue)
// mode 2: v += bias[n]; v = (t==4095) ? 0 : silu(v)   (bwd mixer epilogue)
// mode 3: v += res[m*N+n]                             (residual add)
__global__ __launch_bounds__(256) void gemm_tn(
    const float* __restrict__ A, const float* __restrict__ B,
    float* __restrict__ C, int M, int N, int K, int mode,
    const float* __restrict__ bias, const float* __restrict__ res)
{
    __shared__ float As[16][128];
    __shared__ float Bs[16][128];
    const int tid = threadIdx.x;
    const int bn = blockIdx.x, bm = blockIdx.y;

    const float* Ab = A + (size_t)bm * 128 * K;
    const float* Bb = B + (size_t)bn * 128 * K;

    const int lrow = tid >> 2;          // 0..63
    const int lcol = (tid & 3) << 2;    // 0,4,8,12
    const int tr = (tid >> 4) << 3;     // 0..120
    const int tc = (tid & 15) << 3;     // 0..120

    float acc[8][8];
    #pragma unroll
    for (int i = 0; i < 8; i++)
        #pragma unroll
        for (int j = 0; j < 8; j++) acc[i][j] = 0.0f;

    for (int k0 = 0; k0 < K; k0 += 16) {
        #pragma unroll
        for (int h = 0; h < 2; h++) {
            int r = lrow + h * 64;
            float4 va = *reinterpret_cast<const float4*>(Ab + (size_t)r * K + k0 + lcol);
            As[lcol + 0][r] = va.x; As[lcol + 1][r] = va.y;
            As[lcol + 2][r] = va.z; As[lcol + 3][r] = va.w;
            float4 vb = *reinterpret_cast<const float4*>(Bb + (size_t)r * K + k0 + lcol);
            Bs[lcol + 0][r] = vb.x; Bs[lcol + 1][r] = vb.y;
            Bs[lcol + 2][r] = vb.z; Bs[lcol + 3][r] = vb.w;
        }
        __syncthreads();
        #pragma unroll
        for (int k = 0; k < 16; k++) {
            float ar[8], br[8];
            *(float4*)(ar)     = *(const float4*)(&As[k][tr]);
            *(float4*)(ar + 4) = *(const float4*)(&As[k][tr + 4]);
            *(float4*)(br)     = *(const float4*)(&Bs[k][tc]);
            *(float4*)(br + 4) = *(const float4*)(&Bs[k][tc + 4]);
            #pragma unroll
            for (int i = 0; i < 8; i++)
                #pragma unroll
                for (int j = 0; j < 8; j++)
                    acc[i][j] += ar[i] * br[j];
        }
        __syncthreads();
    }

    #pragma unroll
    for (int i = 0; i < 8; i++) {
        size_t m = (size_t)bm * 128 + tr + i;
        int t = (int)(m & 4095);
        float* Cr = C + m * (size_t)N;
        #pragma unroll
        for (int j = 0; j < 8; j++) {
            int n = bn * 128 + tc + j;
            float v = acc[i][j];
            if (mode == 1)      { v += bias[n]; v = (t == 0)    ? 0.0f : siluf(v); }
            else if (mode == 2) { v += bias[n]; v = (t == 4095) ? 0.0f : siluf(v); }
            else if (mode == 3) { v += res[m * (size_t)N + n]; }
            Cr[n] = v;
        }
    }
}

// ---------------------------------------------------------------------------
// Depthwise causal/anticausal conv with shifts baked in.
// x_proj[b,t,c] = xz[(b*4096+t)*2048 + c]
// cf[b,t,c] = sum_k x_proj[b, t-7+k, c]*wf[c,k] + bf[c]   (fwd, pre-shifted;
//             value at t=0 is garbage but masked in GEMM epilogue mode 1)
// cb[b,t,c] = sum_k x_proj[b, t+7-k, c]*wb[c,k] + bb[c]   (bwd incl. shift+flip;
//             t=4095 masked in mode 2)
__global__ void conv_kernel(const float* __restrict__ xz,
    const float* __restrict__ wf, const float* __restrict__ bf,
    const float* __restrict__ wb, const float* __restrict__ bb,
    float* __restrict__ cf, float* __restrict__ cb)
{
    int idx = blockIdx.x * 256 + threadIdx.x;   // < 32768*1024
    int c = idx & 1023;
    int bt = idx >> 10;
    int t = bt & 4095;
    const float* xp = xz + ((size_t)(bt - t) * 2048) + c;   // (b, 0, c)
    float sf = bf[c], sb = bb[c];
    #pragma unroll
    for (int k = 0; k < 7; k++) {
        int tf = t - 7 + k;
        if (tf >= 0)   sf += xp[(size_t)tf * 2048] * wf[c * 7 + k];
        int tb = t + 7 - k;
        if (tb < 4096) sb += xp[(size_t)tb * 2048] * wb[c * 7 + k];
    }
    cf[idx] = sf;
    cb[idx] = sb;
}

// ---------------------------------------------------------------------------
// y = (yf + yb + x_proj*diag) * silu(z) * gate_scale      (float4 over DI)
__global__ void combine_kernel(const float* __restrict__ xz,
    const float* __restrict__ yf, const float* __restrict__ yb,
    const float* __restrict__ dw, const float* __restrict__ gsp,
    float* __restrict__ y)
{
    int idx = blockIdx.x * 256 + threadIdx.x;   // float4 idx, < 32768*256
    int row = idx >> 8;
    int q = idx & 255;
    float gs = gsp[0];
    const float4 xp = *(const float4*)(xz + (size_t)row * 2048 + q * 4);
    const float4 zz = *(const float4*)(xz + (size_t)row * 2048 + 1024 + q * 4);
    const float4 f  = ((const float4*)yf)[idx];
    const float4 g  = ((const float4*)yb)[idx];
    const float4 d  = ((const float4*)dw)[q];
    float4 o;
    o.x = (f.x + g.x + xp.x * d.x) * siluf(zz.x) * gs;
    o.y = (f.y + g.y + xp.y * d.y) * siluf(zz.y) * gs;
    o.z = (f.z + g.z + xp.z * d.z) * siluf(zz.z) * gs;
    o.w = (f.w + g.w + xp.w * d.w) * siluf(zz.w) * gs;
    ((float4*)y)[idx] = o;
}

// ---------------------------------------------------------------------------
// LayerNorm over D=512 per row. 128 threads/row, float4 per thread.
__global__ void ln_kernel(const float* __restrict__ h,
    const float* __restrict__ g, const float* __restrict__ b,
    float* __restrict__ out)
{
    __shared__ float a1[4], a2[4];
    int row = blockIdx.x;
    int tid = threadIdx.x;  // 128
    const float4 v = ((const float4*)(h + (size_t)row * 512))[tid];
    float s1 = v.x + v.y + v.z + v.w;
    float s2 = v.x * v.x + v.y * v.y + v.z * v.z + v.w * v.w;
    #pragma unroll
    for (int o = 16; o; o >>= 1) {
        s1 += __shfl_xor_sync(0xffffffffu, s1, o);
        s2 += __shfl_xor_sync(0xffffffffu, s2, o);
    }
    if ((tid & 31) == 0) { a1[tid >> 5] = s1; a2[tid >> 5] = s2; }
    __syncthreads();
    s1 = a1[0] + a1[1] + a1[2] + a1[3];
    s2 = a2[0] + a2[1] + a2[2] + a2[3];
    float mu  = s1 * (1.0f / 512.0f);
    float var = s2 * (1.0f / 512.0f) - mu * mu;
    float inv = rsqrtf(var + 1e-5f);
    float4 gg = ((const float4*)g)[tid];
    float4 bb = ((const float4*)b)[tid];
    float4 o;
    o.x = (v.x - mu) * inv * gg.x + bb.x;
    o.y = (v.y - mu) * inv * gg.y + bb.y;
    o.z = (v.z - mu) * inv * gg.z + bb.z;
    o.w = (v.w - mu) * inv * gg.w + bb.w;
    ((float4*)(out + (size_t)row * 512))[tid] = o;
}

// ---------------------------------------------------------------------------
extern "C" void kernel_launch(void* const* d_in, const int* in_sizes, int n_in,
                              void* d_out, int out_size)
{
    (void)in_sizes; (void)n_in; (void)out_size;
    const float* x   = (const float*)d_in[0];
    const float* wi  = (const float*)d_in[1];
    const float* cfw = (const float*)d_in[2];
    const float* cfb = (const float*)d_in[3];
    const float* pfw = (const float*)d_in[4];
    const float* pfb = (const float*)d_in[5];
    const float* cbw = (const float*)d_in[6];
    const float* cbb = (const float*)d_in[7];
    const float* pbw = (const float*)d_in[8];
    const float* pbb = (const float*)d_in[9];
    const float* dw  = (const float*)d_in[10];
    const float* gs  = (const float*)d_in[11];
    const float* ow  = (const float*)d_in[12];
    const float* lng = (const float*)d_in[13];
    const float* lnb = (const float*)d_in[14];
    float* out = (float*)d_out;

    float* S = nullptr;
    cudaGetSymbolAddress((void**)&S, g_scratch);

    // 1) xz = x @ in_proj_w^T   (32768 x 2048 x 512)
    gemm_tn<<<dim3(16, 256), 256>>>(x, wi, S + OFF_XZ, 32768, 2048, 512, 0, nullptr, nullptr);

    // 2) depthwise convs (fwd shifted, bwd anticausal with shift+flip folded)
    conv_kernel<<<(32768 * 1024) / 256, 256>>>(S + OFF_XZ, cfw, cfb, cbw, cbb,
                                               S + OFF_CF, S + OFF_CB);

    // 3) mixers: silu(conv @ W^T + b), masked at t=0 / t=T-1
    gemm_tn<<<dim3(8, 256), 256>>>(S + OFF_CF, pfw, S + OFF_YF, 32768, 1024, 1024, 1, pfb, nullptr);
    gemm_tn<<<dim3(8, 256), 256>>>(S + OFF_CB, pbw, S + OFF_YB, 32768, 1024, 1024, 2, pbb, nullptr);

    // 4) gated combine
    combine_kernel<<<32768, 256>>>(S + OFF_XZ, S + OFF_YF, S + OFF_YB, dw, gs, S + OFF_Y);

    // 5) out_proj + residual
    gemm_tn<<<dim3(4, 256), 256>>>(S + OFF_Y, ow, S + OFF_H, 32768, 512, 1024, 3, nullptr, x);

    // 6) LayerNorm
    ln_kernel<<<32768, 128>>>(S + OFF_H, lng, lnb, out);
}

// round 4
// speedup vs baseline: 4.4300x; 4.4300x over previous
#include <cuda_runtime.h>
#include <cuda_bf16.h>
#include <cstdint>

// B=8, T=4096, D=512, DI=1024, K=7; BT=32768 rows.
// GEMMs: bf16 mma.sync (m16n8k16) tensor cores; residual+LN path fp32.

// ---------------------------------------------------------------------------
// Scratch (bytes). No allocation allowed -> __device__ global.
#define OB_XZB 0ull            // xz bf16        32768 x 2048
#define OB_CFB 134217728ull    // conv fwd bf16  32768 x 1024
#define OB_CBB 201326592ull    // conv bwd bf16
#define OB_YFB 268435456ull    // silu(proj_f) bf16
#define OB_YBB 335544320ull    // silu(proj_b) bf16
#define OB_Y2B 402653184ull    // gated y bf16
#define OB_XB  469762048ull    // x bf16         32768 x 512
#define OB_WIB 503316480ull    // in_proj_w bf16 2048 x 512
#define OB_PFB 505413632ull    // proj_fwd_w bf16
#define OB_PBB 507510784ull    // proj_bwd_w bf16
#define OB_OWB 509607936ull    // out_proj_w bf16 512 x 1024
#define OB_H   510656512ull    // h fp32         32768 x 512
#define SCRATCH_BYTES 577765376ull

__device__ __align__(256) unsigned char g_scratch[SCRATCH_BYTES];

__device__ __forceinline__ float siluf(float v) { return v / (1.0f + expf(-v)); }

__device__ __forceinline__ uint32_t smem_u32(const void* p) {
    uint32_t a;
    asm("{ .reg .u64 t; cvta.to.shared.u64 t, %1; cvt.u32.u64 %0, t; }" : "=r"(a) : "l"(p));
    return a;
}

#define CP16(dst, src) \
    asm volatile("cp.async.cg.shared.global [%0], [%1], 16;" :: "r"(dst), "l"(src))
#define CPCOMMIT() asm volatile("cp.async.commit_group;" ::: "memory")

__device__ __forceinline__ void mma_bf16(float& c0, float& c1, float& c2, float& c3,
                                         uint32_t a0, uint32_t a1, uint32_t a2, uint32_t a3,
                                         uint32_t b0, uint32_t b1) {
    asm volatile(
        "mma.sync.aligned.m16n8k16.row.col.f32.bf16.bf16.f32 "
        "{%0,%1,%2,%3}, {%4,%5,%6,%7}, {%8,%9}, {%0,%1,%2,%3};"
        : "+f"(c0), "+f"(c1), "+f"(c2), "+f"(c3)
        : "r"(a0), "r"(a1), "r"(a2), "r"(a3), "r"(b0), "r"(b1));
}

// smem tile: 128 rows x 32 bf16 cols (64B/row), XOR-swizzled at 16B units.
__device__ __forceinline__ uint32_t tile_off(int row, int k) {
    int u = ((k >> 3) ^ (row & 3));
    return (uint32_t)(row * 64 + u * 16 + (k & 7) * 2);
}

// ---------------------------------------------------------------------------
// bf16 TN GEMM via mma.sync: C[m,n] = sum_k A[m,k]*B[n,k]. Tile 128x128, BK=32.
// mode 0: store bf16
// mode 1: +bias[n]; t==0    ? 0 : silu -> bf16   (fwd mixer, shift folded)
// mode 2: +bias[n]; t==4095 ? 0 : silu -> bf16   (bwd mixer, shift+flip folded)
// mode 3: +res[m,n] -> fp32                      (out_proj + residual)
__global__ __launch_bounds__(256)
void gemm_mma(const __nv_bfloat16* __restrict__ A, const __nv_bfloat16* __restrict__ B,
              void* __restrict__ Cv, int M, int N, int K, int mode,
              const float* __restrict__ bias, const float* __restrict__ res)
{
    __shared__ __align__(128) unsigned char sA[2][8192];
    __shared__ __align__(128) unsigned char sB[2][8192];

    const int tid = threadIdx.x;
    const int wid = tid >> 5, lane = tid & 31;
    const int g = lane >> 2, t = lane & 3;
    const int wm = wid >> 2, wn = wid & 3;         // 2 x 4 warp grid
    const int mBase = wm * 64, nBase = wn * 32;    // 64x32 warp tile
    const int bn = blockIdx.x, bm = blockIdx.y;

    const __nv_bfloat16* Ab = A + (size_t)bm * 128 * K;
    const __nv_bfloat16* Bb = B + (size_t)bn * 128 * K;

    const uint32_t sAu[2] = { smem_u32(sA[0]), smem_u32(sA[1]) };
    const uint32_t sBu[2] = { smem_u32(sB[0]), smem_u32(sB[1]) };

    // loader indices: 512 uint4 per tile, 2 per thread
    const int e0 = tid, e1 = tid + 256;
    const int r0 = e0 >> 2, c0_ = e0 & 3;
    const int r1 = e1 >> 2, c1_ = e1 & 3;
    const uint32_t d0 = (uint32_t)(r0 * 64 + ((c0_ ^ (r0 & 3)) * 16));
    const uint32_t d1 = (uint32_t)(r1 * 64 + ((c1_ ^ (r1 & 3)) * 16));

    float acc[4][4][4];
    #pragma unroll
    for (int i = 0; i < 4; i++)
        #pragma unroll
        for (int j = 0; j < 4; j++)
            #pragma unroll
            for (int q = 0; q < 4; q++) acc[i][j][q] = 0.0f;

    const int nch = K >> 5;

    // prologue: load chunk 0 into buf 0
    {
        CP16(sAu[0] + d0, Ab + (size_t)r0 * K + c0_ * 8);
        CP16(sAu[0] + d1, Ab + (size_t)r1 * K + c1_ * 8);
        CP16(sBu[0] + d0, Bb + (size_t)r0 * K + c0_ * 8);
        CP16(sBu[0] + d1, Bb + (size_t)r1 * K + c1_ * 8);
        CPCOMMIT();
    }

    for (int ch = 0; ch < nch; ch++) {
        if (ch + 1 < nch) {
            const int k0 = (ch + 1) << 5;
            const int nb = (ch + 1) & 1;
            CP16(sAu[nb] + d0, Ab + (size_t)r0 * K + k0 + c0_ * 8);
            CP16(sAu[nb] + d1, Ab + (size_t)r1 * K + k0 + c1_ * 8);
            CP16(sBu[nb] + d0, Bb + (size_t)r0 * K + k0 + c0_ * 8);
            CP16(sBu[nb] + d1, Bb + (size_t)r1 * K + k0 + c1_ * 8);
            CPCOMMIT();
            asm volatile("cp.async.wait_group %0;" :: "n"(1) : "memory");
        } else {
            asm volatile("cp.async.wait_group %0;" :: "n"(0) : "memory");
        }
        __syncthreads();

        const unsigned char* pa = sA[ch & 1];
        const unsigned char* pb = sB[ch & 1];
        #pragma unroll
        for (int ks = 0; ks < 2; ks++) {
            const int kb = ks * 16;
            uint32_t af[4][4];
            #pragma unroll
            for (int mf = 0; mf < 4; mf++) {
                int row = mBase + mf * 16 + g;
                af[mf][0] = *(const uint32_t*)(pa + tile_off(row,     kb + t * 2));
                af[mf][1] = *(const uint32_t*)(pa + tile_off(row + 8, kb + t * 2));
                af[mf][2] = *(const uint32_t*)(pa + tile_off(row,     kb + 8 + t * 2));
                af[mf][3] = *(const uint32_t*)(pa + tile_off(row + 8, kb + 8 + t * 2));
            }
            uint32_t bf[4][2];
            #pragma unroll
            for (int nf = 0; nf < 4; nf++) {
                int rowb = nBase + nf * 8 + g;
                bf[nf][0] = *(const uint32_t*)(pb + tile_off(rowb, kb + t * 2));
                bf[nf][1] = *(const uint32_t*)(pb + tile_off(rowb, kb + 8 + t * 2));
            }
            #pragma unroll
            for (int mf = 0; mf < 4; mf++)
                #pragma unroll
                for (int nf = 0; nf < 4; nf++)
                    mma_bf16(acc[mf][nf][0], acc[mf][nf][1], acc[mf][nf][2], acc[mf][nf][3],
                             af[mf][0], af[mf][1], af[mf][2], af[mf][3],
                             bf[nf][0], bf[nf][1]);
        }
        __syncthreads();
    }

    // Epilogue. c0,c1: row g, cols t*2,t*2+1 ; c2,c3: row g+8.
    #pragma unroll
    for (int mf = 0; mf < 4; mf++) {
        #pragma unroll
        for (int half = 0; half < 2; half++) {
            size_t m = (size_t)bm * 128 + mBase + mf * 16 + g + half * 8;
            int tt = (int)(m & 4095);
            #pragma unroll
            for (int nf = 0; nf < 4; nf++) {
                int col = bn * 128 + nBase + nf * 8 + t * 2;
                float v0 = acc[mf][nf][half * 2 + 0];
                float v1 = acc[mf][nf][half * 2 + 1];
                if (mode == 1) {
                    v0 += bias[col]; v1 += bias[col + 1];
                    if (tt == 0) { v0 = 0.0f; v1 = 0.0f; }
                    else { v0 = siluf(v0); v1 = siluf(v1); }
                } else if (mode == 2) {
                    v0 += bias[col]; v1 += bias[col + 1];
                    if (tt == 4095) { v0 = 0.0f; v1 = 0.0f; }
                    else { v0 = siluf(v0); v1 = siluf(v1); }
                } else if (mode == 3) {
                    v0 += res[m * (size_t)N + col];
                    v1 += res[m * (size_t)N + col + 1];
                }
                if (mode == 3) {
                    float2 o; o.x = v0; o.y = v1;
                    *(float2*)((float*)Cv + m * (size_t)N + col) = o;
                } else {
                    *(__nv_bfloat162*)((__nv_bfloat16*)Cv + m * (size_t)N + col) =
                        __floats2bfloat162_rn(v0, v1);
                }
            }
        }
    }
}

// ---------------------------------------------------------------------------
// fp32 -> bf16 convert (n multiple of 1024; grid = n/1024)
__global__ void to_bf16(const float4* __restrict__ s, uint2* __restrict__ d)
{
    int i = blockIdx.x * 256 + threadIdx.x;
    float4 v = s[i];
    __nv_bfloat162 a = __floats2bfloat162_rn(v.x, v.y);
    __nv_bfloat162 b = __floats2bfloat162_rn(v.z, v.w);
    uint2 o;
    o.x = *reinterpret_cast<uint32_t*>(&a);
    o.y = *reinterpret_cast<uint32_t*>(&b);
    d[i] = o;
}

// ---------------------------------------------------------------------------
// Depthwise convs with shifts baked in (bf16 in, bf16 out).
// cf[t] = fwd conv evaluated at t-1 (pre-shifted; t=0 masked in GEMM mode 1)
// cb[t] = flipped/shifted bwd conv (t=4095 masked in GEMM mode 2)
__global__ void conv_kernel(const __nv_bfloat16* __restrict__ xz,
    const float* __restrict__ wf, const float* __restrict__ bf,
    const float* __restrict__ wb, const float* __restrict__ bb,
    __nv_bfloat16* __restrict__ cf, __nv_bfloat16* __restrict__ cb)
{
    int idx = blockIdx.x * 256 + threadIdx.x;   // < 32768*1024
    int c = idx & 1023;
    int bt = idx >> 10;
    int t = bt & 4095;
    const __nv_bfloat16* xp = xz + (size_t)(bt - t) * 2048 + c;
    float sf = bf[c], sb = bb[c];
    #pragma unroll
    for (int k = 0; k < 7; k++) {
        int tf = t - 7 + k;
        if (tf >= 0)   sf += __bfloat162float(xp[(size_t)tf * 2048]) * wf[c * 7 + k];
        int tb = t + 7 - k;
        if (tb < 4096) sb += __bfloat162float(xp[(size_t)tb * 2048]) * wb[c * 7 + k];
    }
    cf[idx] = __float2bfloat16(sf);
    cb[idx] = __float2bfloat16(sb);
}

// ---------------------------------------------------------------------------
// y = (yf + yb + x_proj*diag) * silu(z) * gate_scale -> bf16
__global__ void combine_kernel(const __nv_bfloat16* __restrict__ xz,
    const __nv_bfloat16* __restrict__ yf, const __nv_bfloat16* __restrict__ yb,
    const float* __restrict__ dw, const float* __restrict__ gsp,
    __nv_bfloat16* __restrict__ y)
{
    int idx = blockIdx.x * 256 + threadIdx.x;   // bf162 granularity: < 32768*512
    int row = idx >> 9;
    int q = idx & 511;
    float gs = gsp[0];
    __nv_bfloat162 xp2 = *(const __nv_bfloat162*)(xz + (size_t)row * 2048 + q * 2);
    __nv_bfloat162 z2  = *(const __nv_bfloat162*)(xz + (size_t)row * 2048 + 1024 + q * 2);
    __nv_bfloat162 f2  = ((const __nv_bfloat162*)yf)[(size_t)row * 512 + q];
    __nv_bfloat162 g2  = ((const __nv_bfloat162*)yb)[(size_t)row * 512 + q];
    float d0 = dw[q * 2], d1 = dw[q * 2 + 1];
    float o0 = (__bfloat162float(f2.x) + __bfloat162float(g2.x) + __bfloat162float(xp2.x) * d0)
               * siluf(__bfloat162float(z2.x)) * gs;
    float o1 = (__bfloat162float(f2.y) + __bfloat162float(g2.y) + __bfloat162float(xp2.y) * d1)
               * siluf(__bfloat162float(z2.y)) * gs;
    ((__nv_bfloat162*)y)[(size_t)row * 512 + q] = __floats2bfloat162_rn(o0, o1);
}

// ---------------------------------------------------------------------------
// LayerNorm over D=512 per row (fp32 in/out).
__global__ void ln_kernel(const float* __restrict__ h,
    const float* __restrict__ g, const float* __restrict__ b,
    float* __restrict__ out)
{
    __shared__ float a1[4], a2[4];
    int row = blockIdx.x;
    int tid = threadIdx.x;  // 128
    const float4 v = ((const float4*)(h + (size_t)row * 512))[tid];
    float s1 = v.x + v.y + v.z + v.w;
    float s2 = v.x * v.x + v.y * v.y + v.z * v.z + v.w * v.w;
    #pragma unroll
    for (int o = 16; o; o >>= 1) {
        s1 += __shfl_xor_sync(0xffffffffu, s1, o);
        s2 += __shfl_xor_sync(0xffffffffu, s2, o);
    }
    if ((tid & 31) == 0) { a1[tid >> 5] = s1; a2[tid >> 5] = s2; }
    __syncthreads();
    s1 = a1[0] + a1[1] + a1[2] + a1[3];
    s2 = a2[0] + a2[1] + a2[2] + a2[3];
    float mu  = s1 * (1.0f / 512.0f);
    float var = s2 * (1.0f / 512.0f) - mu * mu;
    float inv = rsqrtf(var + 1e-5f);
    float4 gg = ((const float4*)g)[tid];
    float4 bb = ((const float4*)b)[tid];
    float4 o;
    o.x = (v.x - mu) * inv * gg.x + bb.x;
    o.y = (v.y - mu) * inv * gg.y + bb.y;
    o.z = (v.z - mu) * inv * gg.z + bb.z;
    o.w = (v.w - mu) * inv * gg.w + bb.w;
    ((float4*)(out + (size_t)row * 512))[tid] = o;
}

// ---------------------------------------------------------------------------
extern "C" void kernel_launch(void* const* d_in, const int* in_sizes, int n_in,
                              void* d_out, int out_size)
{
    (void)in_sizes; (void)n_in; (void)out_size;
    const float* x   = (const float*)d_in[0];
    const float* wi  = (const float*)d_in[1];
    const float* cfw = (const float*)d_in[2];
    const float* cfb = (const float*)d_in[3];
    const float* pfw = (const float*)d_in[4];
    const float* pfb = (const float*)d_in[5];
    const float* cbw = (const float*)d_in[6];
    const float* cbb = (const float*)d_in[7];
    const float* pbw = (const float*)d_in[8];
    const float* pbb = (const float*)d_in[9];
    const float* dw  = (const float*)d_in[10];
    const float* gs  = (const float*)d_in[11];
    const float* ow  = (const float*)d_in[12];
    const float* lng = (const float*)d_in[13];
    const float* lnb = (const float*)d_in[14];
    float* out = (float*)d_out;

    unsigned char* S = nullptr;
    cudaGetSymbolAddress((void**)&S, g_scratch);

    __nv_bfloat16* XZB = (__nv_bfloat16*)(S + OB_XZB);
    __nv_bfloat16* CFB = (__nv_bfloat16*)(S + OB_CFB);
    __nv_bfloat16* CBB = (__nv_bfloat16*)(S + OB_CBB);
    __nv_bfloat16* YFB = (__nv_bfloat16*)(S + OB_YFB);
    __nv_bfloat16* YBB = (__nv_bfloat16*)(S + OB_YBB);
    __nv_bfloat16* Y2B = (__nv_bfloat16*)(S + OB_Y2B);
    __nv_bfloat16* XB  = (__nv_bfloat16*)(S + OB_XB);
    __nv_bfloat16* WIB = (__nv_bfloat16*)(S + OB_WIB);
    __nv_bfloat16* PFB = (__nv_bfloat16*)(S + OB_PFB);
    __nv_bfloat16* PBB = (__nv_bfloat16*)(S + OB_PBB);
    __nv_bfloat16* OWB = (__nv_bfloat16*)(S + OB_OWB);
    float*         H   = (float*)(S + OB_H);

    // 0) fp32 -> bf16 staging
    to_bf16<<<16384, 256>>>((const float4*)x,   (uint2*)XB);   // 32768x512
    to_bf16<<<1024, 256>>>((const float4*)wi,   (uint2*)WIB);  // 2048x512
    to_bf16<<<1024, 256>>>((const float4*)pfw,  (uint2*)PFB);  // 1024x1024
    to_bf16<<<1024, 256>>>((const float4*)pbw,  (uint2*)PBB);  // 1024x1024
    to_bf16<<<512,  256>>>((const float4*)ow,   (uint2*)OWB);  // 512x1024

    // 1) xz = x @ in_proj_w^T  (32768 x 2048 x 512) -> bf16
    gemm_mma<<<dim3(16, 256), 256>>>(XB, WIB, XZB, 32768, 2048, 512, 0, nullptr, nullptr);

    // 2) depthwise convs (shift/flip folded) -> bf16
    conv_kernel<<<(32768 * 1024) / 256, 256>>>(XZB, cfw, cfb, cbw, cbb, CFB, CBB);

    // 3) mixers: silu(conv @ W^T + b), masked at t=0 / t=T-1 -> bf16
    gemm_mma<<<dim3(8, 256), 256>>>(CFB, PFB, YFB, 32768, 1024, 1024, 1, pfb, nullptr);
    gemm_mma<<<dim3(8, 256), 256>>>(CBB, PBB, YBB, 32768, 1024, 1024, 2, pbb, nullptr);

    // 4) gated combine -> bf16
    combine_kernel<<<65536, 256>>>(XZB, YFB, YBB, dw, gs, Y2B);

    // 5) out_proj + residual -> fp32
    gemm_mma<<<dim3(4, 256), 256>>>(Y2B, OWB, H, 32768, 512, 1024, 3, nullptr, x);

    // 6) LayerNorm
    ln_kernel<<<32768, 128>>>(H, lng, lnb, out);
}

// round 10
// speedup vs baseline: 6.0888x; 1.3745x over previous
#include <cuda_runtime.h>
#include <cuda_bf16.h>
#include <cstdint>

// B=8, T=4096, D=512, DI=1024, K=7; BT=32768 rows.
// GEMMs: bf16 mma.sync m16n8k16 + ldmatrix, BK=64, SW128-swizzled smem.

// ---------------------------------------------------------------------------
// Scratch (bytes).
#define OB_XP  0ull            // x_proj bf16    32768 x 1024
#define OB_Z   67108864ull     // z bf16         32768 x 1024
#define OB_CF  134217728ull    // conv fwd bf16
#define OB_CB  201326592ull    // conv bwd bf16
#define OB_YF  268435456ull    // silu(proj_f) bf16
#define OB_Y2  335544320ull    // gated y bf16
#define OB_XB  402653184ull    // x bf16         32768 x 512
#define OB_WIB 436207616ull    // in_proj_w bf16 2048 x 512
#define OB_PFB 438304768ull    // proj_fwd_w bf16 1024x1024
#define OB_PBB 440401920ull    // proj_bwd_w bf16
#define OB_OWB 442499072ull    // out_proj_w bf16 512x1024
#define OB_H   443547648ull    // h fp32         32768 x 512
#define SCRATCH_BYTES 510656512ull

__device__ __align__(256) unsigned char g_scratch[SCRATCH_BYTES];

__device__ __forceinline__ float siluf(float v) { return v / (1.0f + expf(-v)); }

__device__ __forceinline__ uint32_t smem_u32(const void* p) {
    uint32_t a;
    asm("{ .reg .u64 t; cvta.to.shared.u64 t, %1; cvt.u32.u64 %0, t; }" : "=r"(a) : "l"(p));
    return a;
}

#define CP16(dst, src) \
    asm volatile("cp.async.cg.shared.global [%0], [%1], 16;" :: "r"(dst), "l"(src))
#define CPCOMMIT() asm volatile("cp.async.commit_group;" ::: "memory")

__device__ __forceinline__ void mma_bf16(float& c0, float& c1, float& c2, float& c3,
                                         uint32_t a0, uint32_t a1, uint32_t a2, uint32_t a3,
                                         uint32_t b0, uint32_t b1) {
    asm volatile(
        "mma.sync.aligned.m16n8k16.row.col.f32.bf16.bf16.f32 "
        "{%0,%1,%2,%3}, {%4,%5,%6,%7}, {%8,%9}, {%0,%1,%2,%3};"
        : "+f"(c0), "+f"(c1), "+f"(c2), "+f"(c3)
        : "r"(a0), "r"(a1), "r"(a2), "r"(a3), "r"(b0), "r"(b1));
}

__device__ __forceinline__ void ldsm4(uint32_t& r0, uint32_t& r1, uint32_t& r2, uint32_t& r3,
                                      uint32_t addr) {
    asm volatile("ldmatrix.sync.aligned.m8n8.x4.shared.b16 {%0,%1,%2,%3}, [%4];"
                 : "=r"(r0), "=r"(r1), "=r"(r2), "=r"(r3) : "r"(addr));
}

// ---------------------------------------------------------------------------
// bf16 TN GEMM: C[m,n] = sum_k A[m,k]*B[n,k]. Tile 128x128, BK=64, 256 thr.
// Tiles stored as 128 rows x 128B (64 bf16), SW128 swizzle:
//   off(row,k) = row*128 + (((k>>3) ^ (row&7))*16) + (k&7)*2
// mode 0: split store bf16: col<1024 -> C (XP), else -> C2 (Z), stride 1024
// mode 1: +bias[n]; t==0    ? 0 : silu -> bf16  (fwd mixer)
// mode 4: +bias[n]; t==4095 ? 0 : silu = yb; y=(yb+yf+xp*dw)*silu(z)*gs -> bf16
// mode 3: +res[m,n] -> fp32
__global__ __launch_bounds__(256)
void gemm_mma(const __nv_bfloat16* __restrict__ A, const __nv_bfloat16* __restrict__ B,
              void* __restrict__ Cv, void* __restrict__ C2,
              int M, int N, int K, int mode,
              const float* __restrict__ bias, const float* __restrict__ res,
              const __nv_bfloat16* __restrict__ YF, const __nv_bfloat16* __restrict__ XP,
              const __nv_bfloat16* __restrict__ ZB, const float* __restrict__ dw,
              const float* __restrict__ gsp)
{
    extern __shared__ __align__(128) unsigned char dsm[];
    // layout: buf s (s=0,1): A at s*32768, B at s*32768+16384

    const int tid = threadIdx.x;
    const int wid = tid >> 5, lane = tid & 31;
    const int g = lane >> 2, t = lane & 3;
    const int wm = wid >> 2, wn = wid & 3;         // 2 x 4 warp grid
    const int mBase = wm * 64, nBase = wn * 32;    // 64x32 warp tile
    const int bn = blockIdx.x, bm = blockIdx.y;

    const __nv_bfloat16* Ab = A + (size_t)bm * 128 * K;
    const __nv_bfloat16* Bb = B + (size_t)bn * 128 * K;

    const uint32_t sbase = smem_u32(dsm);

    // loader: 1024 uint4 per matrix per chunk, 4 per thread
    int lrow[4]; uint32_t ldst[4];
    #pragma unroll
    for (int i = 0; i < 4; i++) {
        int idx = tid + i * 256;
        int row = idx >> 3, cu = idx & 7;
        lrow[i] = row;
        ldst[i] = (uint32_t)(row * 128 + ((cu ^ (row & 7)) << 4));
    }
    const int lcu = tid & 7;  // source k-unit (8 bf16)

    // ldmatrix per-lane geometry
    const int arow_l = (lane & 15);
    const int akk_l  = (lane >> 4);            // in 8-elem units
    const int brow_l = (lane & 7) + ((lane >> 4) << 3);
    const int bkk_l  = ((lane >> 3) & 1);

    float acc[4][4][4];
    #pragma unroll
    for (int i = 0; i < 4; i++)
        #pragma unroll
        for (int j = 0; j < 4; j++)
            #pragma unroll
            for (int q = 0; q < 4; q++) acc[i][j][q] = 0.0f;

    const int nch = K >> 6;

    // prologue: chunk 0 -> buf 0
    #pragma unroll
    for (int i = 0; i < 4; i++) {
        CP16(sbase + ldst[i],         Ab + (size_t)lrow[i] * K + lcu * 8);
        CP16(sbase + 16384 + ldst[i], Bb + (size_t)lrow[i] * K + lcu * 8);
    }
    CPCOMMIT();

    for (int ch = 0; ch < nch; ch++) {
        if (ch + 1 < nch) {
            const int k0 = (ch + 1) << 6;
            const uint32_t nb = (uint32_t)((ch + 1) & 1) * 32768u;
            #pragma unroll
            for (int i = 0; i < 4; i++) {
                CP16(sbase + nb + ldst[i],         Ab + (size_t)lrow[i] * K + k0 + lcu * 8);
                CP16(sbase + nb + 16384 + ldst[i], Bb + (size_t)lrow[i] * K + k0 + lcu * 8);
            }
            CPCOMMIT();
            asm volatile("cp.async.wait_group %0;" :: "n"(1) : "memory");
        } else {
            asm volatile("cp.async.wait_group %0;" :: "n"(0) : "memory");
        }
        __syncthreads();

        const uint32_t pa = sbase + (uint32_t)(ch & 1) * 32768u;
        const uint32_t pb = pa + 16384u;

        #pragma unroll
        for (int ks = 0; ks < 4; ks++) {
            uint32_t af[4][4];
            #pragma unroll
            for (int mf = 0; mf < 4; mf++) {
                int row = mBase + mf * 16 + arow_l;
                int kk = ks * 2 + akk_l;
                uint32_t off = (uint32_t)(row * 128 + ((kk ^ (row & 7)) << 4));
                ldsm4(af[mf][0], af[mf][1], af[mf][2], af[mf][3], pa + off);
            }
            uint32_t bf[4][2];
            #pragma unroll
            for (int p = 0; p < 2; p++) {
                int row = nBase + p * 16 + brow_l;
                int kk = ks * 2 + bkk_l;
                uint32_t off = (uint32_t)(row * 128 + ((kk ^ (row & 7)) << 4));
                ldsm4(bf[p * 2][0], bf[p * 2][1], bf[p * 2 + 1][0], bf[p * 2 + 1][1], pb + off);
            }
            #pragma unroll
            for (int mf = 0; mf < 4; mf++)
                #pragma unroll
                for (int nf = 0; nf < 4; nf++)
                    mma_bf16(acc[mf][nf][0], acc[mf][nf][1], acc[mf][nf][2], acc[mf][nf][3],
                             af[mf][0], af[mf][1], af[mf][2], af[mf][3],
                             bf[nf][0], bf[nf][1]);
        }
        __syncthreads();
    }

    // Epilogue. c0,c1: row g, cols t*2,t*2+1 ; c2,c3: row g+8.
    const float gsv = (mode == 4) ? gsp[0] : 0.0f;
    #pragma unroll
    for (int mf = 0; mf < 4; mf++) {
        #pragma unroll
        for (int half = 0; half < 2; half++) {
            size_t m = (size_t)bm * 128 + mBase + mf * 16 + g + half * 8;
            int tt = (int)(m & 4095);
            #pragma unroll
            for (int nf = 0; nf < 4; nf++) {
                int col = bn * 128 + nBase + nf * 8 + t * 2;
                float v0 = acc[mf][nf][half * 2 + 0];
                float v1 = acc[mf][nf][half * 2 + 1];
                if (mode == 0) {
                    __nv_bfloat162 o = __floats2bfloat162_rn(v0, v1);
                    if (col < 1024)
                        *(__nv_bfloat162*)((__nv_bfloat16*)Cv + m * 1024 + col) = o;
                    else
                        *(__nv_bfloat162*)((__nv_bfloat16*)C2 + m * 1024 + (col - 1024)) = o;
                } else if (mode == 1) {
                    v0 += bias[col]; v1 += bias[col + 1];
                    if (tt == 0) { v0 = 0.0f; v1 = 0.0f; }
                    else { v0 = siluf(v0); v1 = siluf(v1); }
                    *(__nv_bfloat162*)((__nv_bfloat16*)Cv + m * (size_t)N + col) =
                        __floats2bfloat162_rn(v0, v1);
                } else if (mode == 4) {
                    v0 += bias[col]; v1 += bias[col + 1];
                    if (tt == 4095) { v0 = 0.0f; v1 = 0.0f; }
                    else { v0 = siluf(v0); v1 = siluf(v1); }
                    __nv_bfloat162 yf2 = *(const __nv_bfloat162*)(YF + m * 1024 + col);
                    __nv_bfloat162 xp2 = *(const __nv_bfloat162*)(XP + m * 1024 + col);
                    __nv_bfloat162 z2  = *(const __nv_bfloat162*)(ZB + m * 1024 + col);
                    float y0 = (v0 + __bfloat162float(yf2.x)
                                + __bfloat162float(xp2.x) * dw[col])
                               * siluf(__bfloat162float(z2.x)) * gsv;
                    float y1 = (v1 + __bfloat162float(yf2.y)
                                + __bfloat162float(xp2.y) * dw[col + 1])
                               * siluf(__bfloat162float(z2.y)) * gsv;
                    *(__nv_bfloat162*)((__nv_bfloat16*)Cv + m * (size_t)N + col) =
                        __floats2bfloat162_rn(y0, y1);
                } else { // mode 3
                    v0 += res[m * (size_t)N + col];
                    v1 += res[m * (size_t)N + col + 1];
                    float2 o; o.x = v0; o.y = v1;
                    *(float2*)((float*)Cv + m * (size_t)N + col) = o;
                }
            }
        }
    }
}

// ---------------------------------------------------------------------------
// fp32 -> bf16 convert (grid*256*4 elements)
__global__ void to_bf16(const float4* __restrict__ s, uint2* __restrict__ d)
{
    int i = blockIdx.x * 256 + threadIdx.x;
    float4 v = s[i];
    __nv_bfloat162 a = __floats2bfloat162_rn(v.x, v.y);
    __nv_bfloat162 b = __floats2bfloat162_rn(v.z, v.w);
    uint2 o;
    o.x = *reinterpret_cast<uint32_t*>(&a);
    o.y = *reinterpret_cast<uint32_t*>(&b);
    d[i] = o;
}

// ---------------------------------------------------------------------------
// Depthwise convs with shifts baked in. Reads XP (stride 1024 bf16).
__global__ void conv_kernel(const __nv_bfloat16* __restrict__ xp0,
    const float* __restrict__ wf, const float* __restrict__ bf,
    const float* __restrict__ wb, const float* __restrict__ bb,
    __nv_bfloat16* __restrict__ cf, __nv_bfloat16* __restrict__ cb)
{
    int idx = blockIdx.x * 256 + threadIdx.x;   // < 32768*1024
    int c = idx & 1023;
    int bt = idx >> 10;
    int t = bt & 4095;
    const __nv_bfloat16* xp = xp0 + (size_t)(bt - t) * 1024 + c;
    float sf = bf[c], sb = bb[c];
    #pragma unroll
    for (int k = 0; k < 7; k++) {
        int tf = t - 7 + k;
        if (tf >= 0)   sf += __bfloat162float(xp[(size_t)tf * 1024]) * wf[c * 7 + k];
        int tb = t + 7 - k;
        if (tb < 4096) sb += __bfloat162float(xp[(size_t)tb * 1024]) * wb[c * 7 + k];
    }
    cf[idx] = __float2bfloat16(sf);
    cb[idx] = __float2bfloat16(sb);
}

// ---------------------------------------------------------------------------
// LayerNorm over D=512 per row (fp32 in/out).
__global__ void ln_kernel(const float* __restrict__ h,
    const float* __restrict__ g, const float* __restrict__ b,
    float* __restrict__ out)
{
    __shared__ float a1[4], a2[4];
    int row = blockIdx.x;
    int tid = threadIdx.x;  // 128
    const float4 v = ((const float4*)(h + (size_t)row * 512))[tid];
    float s1 = v.x + v.y + v.z + v.w;
    float s2 = v.x * v.x + v.y * v.y + v.z * v.z + v.w * v.w;
    #pragma unroll
    for (int o = 16; o; o >>= 1) {
        s1 += __shfl_xor_sync(0xffffffffu, s1, o);
        s2 += __shfl_xor_sync(0xffffffffu, s2, o);
    }
    if ((tid & 31) == 0) { a1[tid >> 5] = s1; a2[tid >> 5] = s2; }
    __syncthreads();
    s1 = a1[0] + a1[1] + a1[2] + a1[3];
    s2 = a2[0] + a2[1] + a2[2] + a2[3];
    float mu  = s1 * (1.0f / 512.0f);
    float var = s2 * (1.0f / 512.0f) - mu * mu;
    float inv = rsqrtf(var + 1e-5f);
    float4 gg = ((const float4*)g)[tid];
    float4 bb = ((const float4*)b)[tid];
    float4 o;
    o.x = (v.x - mu) * inv * gg.x + bb.x;
    o.y = (v.y - mu) * inv * gg.y + bb.y;
    o.z = (v.z - mu) * inv * gg.z + bb.z;
    o.w = (v.w - mu) * inv * gg.w + bb.w;
    ((float4*)(out + (size_t)row * 512))[tid] = o;
}

// ---------------------------------------------------------------------------
extern "C" void kernel_launch(void* const* d_in, const int* in_sizes, int n_in,
                              void* d_out, int out_size)
{
    (void)in_sizes; (void)n_in; (void)out_size;
    const float* x   = (const float*)d_in[0];
    const float* wi  = (const float*)d_in[1];
    const float* cfw = (const float*)d_in[2];
    const float* cfb = (const float*)d_in[3];
    const float* pfw = (const float*)d_in[4];
    const float* pfb = (const float*)d_in[5];
    const float* cbw = (const float*)d_in[6];
    const float* cbb = (const float*)d_in[7];
    const float* pbw = (const float*)d_in[8];
    const float* pbb = (const float*)d_in[9];
    const float* dw  = (const float*)d_in[10];
    const float* gs  = (const float*)d_in[11];
    const float* ow  = (const float*)d_in[12];
    const float* lng = (const float*)d_in[13];
    const float* lnb = (const float*)d_in[14];
    float* out = (float*)d_out;

    unsigned char* S = nullptr;
    cudaGetSymbolAddress((void**)&S, g_scratch);

    __nv_bfloat16* XP  = (__nv_bfloat16*)(S + OB_XP);
    __nv_bfloat16* ZB  = (__nv_bfloat16*)(S + OB_Z);
    __nv_bfloat16* CF  = (__nv_bfloat16*)(S + OB_CF);
    __nv_bfloat16* CB  = (__nv_bfloat16*)(S + OB_CB);
    __nv_bfloat16* YF  = (__nv_bfloat16*)(S + OB_YF);
    __nv_bfloat16* Y2  = (__nv_bfloat16*)(S + OB_Y2);
    __nv_bfloat16* XB  = (__nv_bfloat16*)(S + OB_XB);
    __nv_bfloat16* WIB = (__nv_bfloat16*)(S + OB_WIB);
    __nv_bfloat16* PFB = (__nv_bfloat16*)(S + OB_PFB);
    __nv_bfloat16* PBB = (__nv_bfloat16*)(S + OB_PBB);
    __nv_bfloat16* OWB = (__nv_bfloat16*)(S + OB_OWB);
    float*         H   = (float*)(S + OB_H);

    cudaFuncSetAttribute(gemm_mma, cudaFuncAttributeMaxDynamicSharedMemorySize, 65536);
    const int SMEM = 65536;

    // 0) fp32 -> bf16 staging
    to_bf16<<<16384, 256>>>((const float4*)x,   (uint2*)XB);   // 32768x512
    to_bf16<<<1024, 256>>>((const float4*)wi,   (uint2*)WIB);  // 2048x512
    to_bf16<<<1024, 256>>>((const float4*)pfw,  (uint2*)PFB);  // 1024x1024
    to_bf16<<<1024, 256>>>((const float4*)pbw,  (uint2*)PBB);  // 1024x1024
    to_bf16<<<512,  256>>>((const float4*)ow,   (uint2*)OWB);  // 512x1024

    // 1) xz = x @ in_proj_w^T  -> split XP | Z (bf16)
    gemm_mma<<<dim3(16, 256), 256, SMEM>>>(XB, WIB, XP, ZB, 32768, 2048, 512, 0,
        nullptr, nullptr, nullptr, nullptr, nullptr, nullptr, nullptr);

    // 2) depthwise convs (shift/flip folded) -> bf16
    conv_kernel<<<(32768 * 1024) / 256, 256>>>(XP, cfw, cfb, cbw, cbb, CF, CB);

    // 3a) fwd mixer: silu(cf @ Wf^T + b), t==0 masked -> YF
    gemm_mma<<<dim3(8, 256), 256, SMEM>>>(CF, PFB, YF, nullptr, 32768, 1024, 1024, 1,
        pfb, nullptr, nullptr, nullptr, nullptr, nullptr, nullptr);

    // 3b) bwd mixer fused with combine -> Y2
    gemm_mma<<<dim3(8, 256), 256, SMEM>>>(CB, PBB, Y2, nullptr, 32768, 1024, 1024, 4,
        pbb, nullptr, YF, XP, ZB, dw, gs);

    // 4) out_proj + residual -> fp32 H
    gemm_mma<<<dim3(4, 256), 256, SMEM>>>(Y2, OWB, H, nullptr, 32768, 512, 1024, 3,
        nullptr, x, nullptr, nullptr, nullptr, nullptr, nullptr);

    // 5) LayerNorm
    ln_kernel<<<32768, 128>>>(H, lng, lnb, out);
}